// round 7
// baseline (speedup 1.0000x reference)
#include <cuda_runtime.h>
#include <cstdint>

#define NPLANES 16384      // 64*256
#define HM 50
#define WM 50
#define HH 56
#define NTOT 51380224      // 64*256*56*56
#define NVEC (NTOT/4)      // 12845056 float4s
#define NVEC2 (NVEC/2)     // 6422528
#define ROWWORDS (NPLANES*HH)
#define PLANE_ELEMS (HM*WM)   // 2500 floats
#define PLANE_V4 625
#define MASK_BLOCKS (NPLANES/8)   // 2048

typedef unsigned long long ull;

__device__ ull g_blocked[ROWWORDS];     // 7.34 MB: 64-bit dilated row mask per row
__device__ ull g_count = 0ULL;          // invariant: 0 at entry of every launch
__device__ unsigned g_done = 0u;        // completion ticket, reset each launch
__device__ float g_scale;

// One warp per plane, 8 planes per 256-thread block.
// ALL 20 LDG.128s per lane are issued before any data-dependent test
// (MLP=20), then one min-tree + one rare branch. Slow path re-scans the
// register array (fully unrolled, static indexing) and does
// atomicOr(0x7F << col) into smem rows -- horizontal 7-dilation fused in.
__global__ __launch_bounds__(256, 2) void mask_kernel(const float* __restrict__ mask_u) {
    const float gamma = (float)(0.1 / 49.0 * 3136.0 / 2500.0);

    __shared__ ull rows[8][HM];
    __shared__ int wsum[8];

    const int tid  = threadIdx.x;
    const int warp = tid >> 5;
    const int lane = tid & 31;
    const int plane = blockIdx.x * 8 + warp;

    #pragma unroll
    for (int r = lane; r < HM; r += 32) rows[warp][r] = 0ULL;
    __syncwarp();

    const float4* p = (const float4*)(mask_u + (size_t)plane * PLANE_ELEMS);

    // ---- front-batched loads: 20 independent LDG.128 per lane ----
    float4 v[20];
    #pragma unroll
    for (int c = 0; c < 20; c++) {
        int i = lane + c * 32;
        v[c] = make_float4(1.f, 1.f, 1.f, 1.f);
        if (i < PLANE_V4) v[c] = __ldcs(&p[i]);   // predicate only live for c==19
    }

    // ---- min tree over 80 values ----
    float m = 1e30f;
    #pragma unroll
    for (int c = 0; c < 20; c++)
        m = fminf(m, fminf(fminf(v[c].x, v[c].y), fminf(v[c].z, v[c].w)));

    if (m < gamma) {                               // rare (~18% of warps, ~0.6% lanes)
        #pragma unroll
        for (int c = 0; c < 20; c++) {
            int base = (lane + c * 32) * 4;
            if (v[c].x < gamma) { int e = base;     atomicOr(&rows[warp][e / WM], 0x7FULL << (e % WM)); }
            if (v[c].y < gamma) { int e = base + 1; atomicOr(&rows[warp][e / WM], 0x7FULL << (e % WM)); }
            if (v[c].z < gamma) { int e = base + 2; atomicOr(&rows[warp][e / WM], 0x7FULL << (e % WM)); }
            if (v[c].w < gamma) { int e = base + 3; atomicOr(&rows[warp][e / WM], 0x7FULL << (e % WM)); }
        }
    }
    __syncwarp();

    // ---- vertical OR over window [h-6, h], write dilated mask, popcount ----
    int cnt = 0;
    #pragma unroll
    for (int hh = 0; hh < 2; hh++) {
        int h = lane + hh * 32;
        if (h < HH) {
            int a = h - 6; if (a < 0) a = 0;
            int b = h;     if (b > HM - 1) b = HM - 1;
            ull o = 0ULL;
            for (int r = a; r <= b; r++) o |= rows[warp][r];
            g_blocked[(size_t)plane * HH + h] = o;
            cnt += __popcll(o);
        }
    }
    #pragma unroll
    for (int off = 16; off; off >>= 1)
        cnt += __shfl_down_sync(0xFFFFFFFFu, cnt, off);
    if (lane == 0) wsum[warp] = cnt;
    __syncthreads();

    if (tid == 0) {
        int t = 0;
        #pragma unroll
        for (int w = 0; w < 8; w++) t += wsum[w];
        atomicAdd(&g_count, (ull)t);
        __threadfence();
        unsigned ticket = atomicAdd(&g_done, 1u);
        if (ticket == MASK_BLOCKS - 1) {          // last block: finalize + reset
            ull c = atomicAdd(&g_count, 0ULL);
            g_scale = (float)((double)NTOT / (double)(NTOT - (long long)c));
            g_count = 0ULL;
            g_done  = 0u;
        }
    }
}

// Elementwise apply: out = x * (1-blocked) * scale. 2 float4s per thread
// (proven 77%-DRAM form from R4), streaming hints on the 410 MB x/out traffic.
__global__ __launch_bounds__(256) void apply_kernel(const float4* __restrict__ x4,
                                                    float4* __restrict__ out4) {
    const int v0 = blockIdx.x * blockDim.x + threadIdx.x;
    const float s = g_scale;

    #pragma unroll
    for (int half = 0; half < 2; half++) {
        int v = v0 + half * NVEC2;
        int rowg = v / 14;               // global row == plane*56 + h
        int c4   = v - rowg * 14;
        unsigned bits = (unsigned)(g_blocked[rowg] >> (c4 * 4)) & 0xFu;

        float4 xi = __ldcs(&x4[v]);
        float4 o;
        o.x = (bits & 1u) ? 0.0f : xi.x * s;
        o.y = (bits & 2u) ? 0.0f : xi.y * s;
        o.z = (bits & 4u) ? 0.0f : xi.z * s;
        o.w = (bits & 8u) ? 0.0f : xi.w * s;
        __stcs(&out4[v], o);
    }
}

extern "C" void kernel_launch(void* const* d_in, const int* in_sizes, int n_in,
                              void* d_out, int out_size) {
    const float* x      = (const float*)d_in[0];
    const float* mask_u = (const float*)d_in[1];
    float* out          = (float*)d_out;

    mask_kernel<<<MASK_BLOCKS, 256>>>(mask_u);
    apply_kernel<<<NVEC2 / 256, 256>>>((const float4*)x, (float4*)out);
}

// round 12
// speedup vs baseline: 1.0227x; 1.0227x over previous
#include <cuda_runtime.h>
#include <cstdint>

#define NPLANES 16384          // 64*256
#define HM 50
#define WM 50
#define HH 56
#define NTOT 51380224          // 64*256*56*56
#define NVEC (NTOT/4)          // 12845056 float4s (x / out)
#define NVEC2 (NVEC/2)
#define PLANE_ELEMS (HM*WM)    // 2500
#define MV4 (NPLANES*PLANE_ELEMS/4)   // 10,240,000 mask float4s
#define MV4H (MV4/2)                  // 5,120,000
#define DIL_BLOCKS (NPLANES/8)        // 2048

typedef unsigned long long ull;

__device__ ull g_raw[NPLANES * HM];      // 6.5 MB, horizontally-dilated hit rows
                                         // invariant: all-zero at entry (static init
                                         // + re-zeroed by dilate_kernel each replay)
__device__ ull g_blocked[NPLANES * HH];  // 7.3 MB, fully dilated row masks
__device__ ull g_count = 0ULL;
__device__ unsigned g_done = 0u;
__device__ float g_scale;

// Pure streaming scan: 2 float4s/thread, zero index math on the fast path.
// Rare hit (~0.26% of elements): atomicOr(0x7F << col) into g_raw — the
// horizontal 7-dilation is fused into the sparse scatter.
__global__ __launch_bounds__(256) void scan_kernel(const float4* __restrict__ mu4) {
    const float gamma = (float)(0.1 / 49.0 * 3136.0 / 2500.0);
    const int t = blockIdx.x * blockDim.x + threadIdx.x;

    #pragma unroll
    for (int half = 0; half < 2; half++) {
        int i4 = t + half * MV4H;
        float4 v = __ldcs(&mu4[i4]);
        float m = fminf(fminf(v.x, v.y), fminf(v.z, v.w));
        if (m < gamma) {                                   // rare
            int e0 = i4 * 4;
            #pragma unroll
            for (int j = 0; j < 4; j++) {
                float f = (j == 0) ? v.x : (j == 1) ? v.y : (j == 2) ? v.z : v.w;
                if (f < gamma) {
                    int e = e0 + j;
                    int plane = e / PLANE_ELEMS;
                    int rem   = e - plane * PLANE_ELEMS;
                    int r     = rem / WM;
                    int c     = rem - r * WM;
                    atomicOr(&g_raw[plane * HM + r], 0x7FULL << c);
                }
            }
        }
    }
}

// One warp per plane: vertical OR over [h-6, h], write g_blocked, re-zero
// g_raw for the next replay, popcount + global count; last block finalizes
// g_scale and resets the counters.
__global__ __launch_bounds__(256) void dilate_kernel() {
    __shared__ ull rows[8][HM];
    __shared__ int wsum[8];

    const int tid  = threadIdx.x;
    const int warp = tid >> 5;
    const int lane = tid & 31;
    const int plane = blockIdx.x * 8 + warp;

    ull* praw = &g_raw[(size_t)plane * HM];
    rows[warp][lane] = praw[lane];
    if (lane < HM - 32) rows[warp][lane + 32] = praw[lane + 32];
    __syncwarp();
    praw[lane] = 0ULL;                       // restore invariant for next replay
    if (lane < HM - 32) praw[lane + 32] = 0ULL;

    int cnt = 0;
    #pragma unroll
    for (int hh = 0; hh < 2; hh++) {
        int h = lane + hh * 32;
        if (h < HH) {
            int a = h - 6; if (a < 0) a = 0;
            int b = h;     if (b > HM - 1) b = HM - 1;
            ull o = 0ULL;
            for (int r = a; r <= b; r++) o |= rows[warp][r];
            g_blocked[(size_t)plane * HH + h] = o;
            cnt += __popcll(o);
        }
    }
    #pragma unroll
    for (int off = 16; off; off >>= 1)
        cnt += __shfl_down_sync(0xFFFFFFFFu, cnt, off);
    if (lane == 0) wsum[warp] = cnt;
    __syncthreads();

    if (tid == 0) {
        int s = 0;
        #pragma unroll
        for (int w = 0; w < 8; w++) s += wsum[w];
        atomicAdd(&g_count, (ull)s);
        __threadfence();
        unsigned ticket = atomicAdd(&g_done, 1u);
        if (ticket == DIL_BLOCKS - 1) {
            ull c = atomicAdd(&g_count, 0ULL);
            g_scale = (float)((double)NTOT / (double)(NTOT - (long long)c));
            g_count = 0ULL;
            g_done  = 0u;
        }
    }
}

// Elementwise apply (proven R4 form): out = x * (1-blocked) * scale.
__global__ __launch_bounds__(256) void apply_kernel(const float4* __restrict__ x4,
                                                    float4* __restrict__ out4) {
    const int v0 = blockIdx.x * blockDim.x + threadIdx.x;
    const float s = g_scale;

    #pragma unroll
    for (int half = 0; half < 2; half++) {
        int v = v0 + half * NVEC2;
        int rowg = v / 14;               // global row == plane*56 + h
        int c4   = v - rowg * 14;
        unsigned bits = (unsigned)(g_blocked[rowg] >> (c4 * 4)) & 0xFu;

        float4 xi = __ldcs(&x4[v]);
        float4 o;
        o.x = (bits & 1u) ? 0.0f : xi.x * s;
        o.y = (bits & 2u) ? 0.0f : xi.y * s;
        o.z = (bits & 4u) ? 0.0f : xi.z * s;
        o.w = (bits & 8u) ? 0.0f : xi.w * s;
        __stcs(&out4[v], o);
    }
}

extern "C" void kernel_launch(void* const* d_in, const int* in_sizes, int n_in,
                              void* d_out, int out_size) {
    const float* x      = (const float*)d_in[0];
    const float* mask_u = (const float*)d_in[1];
    float* out          = (float*)d_out;

    scan_kernel<<<MV4H / 256, 256>>>((const float4*)mask_u);
    dilate_kernel<<<DIL_BLOCKS, 256>>>();
    apply_kernel<<<NVEC2 / 256, 256>>>((const float4*)x, (float4*)out);
}

// round 13
// speedup vs baseline: 1.0612x; 1.0376x over previous
#include <cuda_runtime.h>
#include <cstdint>

#define NPLANES 16384          // 64*256
#define HM 50
#define WM 50
#define HH 56
#define NTOT 51380224          // 64*256*56*56
#define NVEC (NTOT/4)          // 12845056 float4s (x / out)
#define NVEC2 (NVEC/2)
#define PLANE_ELEMS (HM*WM)    // 2500
#define PAIR_V4 1250           // float4s per 2-plane pair
#define MASK_BLOCKS (NPLANES/2)   // 8192

typedef unsigned long long ull;

__device__ ull g_blocked[NPLANES * HH];  // 7.3 MB, dilated 64-bit row masks
__device__ ull g_count = 0ULL;           // invariant: 0 at entry of every launch
__device__ unsigned g_done = 0u;         // ticket, reset each launch
__device__ float g_scale;

// One block per 2 planes. Phase 1: 5 front-batched LDG.128 per thread (MLP=5),
// min-tree, rare smem atomicOr(0x7F<<col) -- horizontal dilation fused into
// the sparse insert. Phase 2: in-block vertical 7-OR -> g_blocked + popcount.
// Last-finishing block computes g_scale and resets counters (replay-safe).
__global__ __launch_bounds__(256) void mask_kernel(const float* __restrict__ mask_u) {
    const float gamma = (float)(0.1 / 49.0 * 3136.0 / 2500.0);

    __shared__ ull rows[2][HM];
    __shared__ int bsum;

    const int tid = threadIdx.x;

    // zero smem rows
    if (tid < 2 * HM) ((ull*)rows)[tid] = 0ULL;
    if (tid == 0) bsum = 0;
    __syncthreads();

    const float4* p = (const float4*)(mask_u + (size_t)blockIdx.x * (2 * PLANE_ELEMS));

    // ---- phase 1: front-batched loads (4 unconditional + 1 predicated) ----
    float4 v0 = __ldcs(&p[tid]);
    float4 v1 = __ldcs(&p[tid + 256]);
    float4 v2 = __ldcs(&p[tid + 512]);
    float4 v3 = __ldcs(&p[tid + 768]);
    float4 v4 = make_float4(1.f, 1.f, 1.f, 1.f);
    if (tid < PAIR_V4 - 1024) v4 = __ldcs(&p[tid + 1024]);   // 226 tail threads

    float m01 = fminf(fminf(fminf(v0.x, v0.y), fminf(v0.z, v0.w)),
                      fminf(fminf(v1.x, v1.y), fminf(v1.z, v1.w)));
    float m23 = fminf(fminf(fminf(v2.x, v2.y), fminf(v2.z, v2.w)),
                      fminf(fminf(v3.x, v3.y), fminf(v3.z, v3.w)));
    float m4  = fminf(fminf(v4.x, v4.y), fminf(v4.z, v4.w));

    if (fminf(fminf(m01, m23), m4) < gamma) {        // rare (~6% of threads' blocks)
        const float4 vs[5] = {v0, v1, v2, v3, v4};
        #pragma unroll
        for (int c = 0; c < 5; c++) {
            int base = (tid + c * 256) * 4;
            #pragma unroll
            for (int j = 0; j < 4; j++) {
                float f = (j == 0) ? vs[c].x : (j == 1) ? vs[c].y
                        : (j == 2) ? vs[c].z : vs[c].w;
                if (f < gamma) {
                    int e = base + j;                 // 0..4999
                    int pl  = (e >= PLANE_ELEMS);
                    int rem = e - pl * PLANE_ELEMS;
                    int r   = rem / WM;
                    int cc  = rem - r * WM;
                    atomicOr(&rows[pl][r], 0x7FULL << cc);
                }
            }
        }
    }
    __syncthreads();

    // ---- phase 2: vertical OR over [h-6, h] for 112 output rows ----
    int cnt = 0;
    if (tid < 2 * HH) {
        int pl = tid / HH;
        int h  = tid - pl * HH;
        int a = h - 6; if (a < 0) a = 0;
        int b = h;     if (b > HM - 1) b = HM - 1;
        ull o = 0ULL;
        for (int r = a; r <= b; r++) o |= rows[pl][r];
        g_blocked[((size_t)blockIdx.x * 2 + pl) * HH + h] = o;
        cnt = __popcll(o);
    }
    #pragma unroll
    for (int off = 16; off; off >>= 1)
        cnt += __shfl_down_sync(0xFFFFFFFFu, cnt, off);
    if ((tid & 31) == 0 && cnt) atomicAdd(&bsum, cnt);
    __syncthreads();

    if (tid == 0) {
        atomicAdd(&g_count, (ull)bsum);
        __threadfence();
        unsigned ticket = atomicAdd(&g_done, 1u);
        if (ticket == MASK_BLOCKS - 1) {             // last block: finalize + reset
            ull c = atomicAdd(&g_count, 0ULL);
            g_scale = (float)((double)NTOT / (double)(NTOT - (long long)c));
            g_count = 0ULL;
            g_done  = 0u;
        }
    }
}

// Elementwise apply (proven R4 form, 77% DRAM): out = x * (1-blocked) * scale.
__global__ __launch_bounds__(256) void apply_kernel(const float4* __restrict__ x4,
                                                    float4* __restrict__ out4) {
    const int v0 = blockIdx.x * blockDim.x + threadIdx.x;
    const float s = g_scale;

    #pragma unroll
    for (int half = 0; half < 2; half++) {
        int v = v0 + half * NVEC2;
        int rowg = v / 14;               // global row == plane*56 + h
        int c4   = v - rowg * 14;
        unsigned bits = (unsigned)(g_blocked[rowg] >> (c4 * 4)) & 0xFu;

        float4 xi = __ldcs(&x4[v]);
        float4 o;
        o.x = (bits & 1u) ? 0.0f : xi.x * s;
        o.y = (bits & 2u) ? 0.0f : xi.y * s;
        o.z = (bits & 4u) ? 0.0f : xi.z * s;
        o.w = (bits & 8u) ? 0.0f : xi.w * s;
        __stcs(&out4[v], o);
    }
}

extern "C" void kernel_launch(void* const* d_in, const int* in_sizes, int n_in,
                              void* d_out, int out_size) {
    const float* x      = (const float*)d_in[0];
    const float* mask_u = (const float*)d_in[1];
    float* out          = (float*)d_out;

    mask_kernel<<<MASK_BLOCKS, 256>>>(mask_u);
    apply_kernel<<<NVEC2 / 256, 256>>>((const float4*)x, (float4*)out);
}